// round 3
// baseline (speedup 1.0000x reference)
#include <cuda_runtime.h>
#include <cstdint>

#define N_TOK 2304
#define DIMX 384
#define NHEADS 8
#define KD 32
#define DV 128
#define DH 1024
#define SCALE_F 0.17677669529663687f

// Scratch (allocation-free rule: __device__ globals)
__device__ float g_Q[NHEADS * N_TOK * KD];   // [h][n][32]
__device__ float g_K[NHEADS * N_TOK * KD];   // [h][n][32]
__device__ float g_V[NHEADS * N_TOK * DV];   // [h][n][128]
__device__ float g_O[N_TOK * DH];            // [n][h*128+d]

// ---------------------------------------------------------------------------
// helpers
// ---------------------------------------------------------------------------
__device__ __forceinline__ uint32_t f2tf(float f) {
    uint32_t u;
    asm("cvt.rna.tf32.f32 %0, %1;" : "=r"(u) : "f"(f));
    return u;
}

__device__ __forceinline__ void mma8(float* d,
                                     uint32_t a0, uint32_t a1, uint32_t a2, uint32_t a3,
                                     uint32_t b0, uint32_t b1)
{
    asm volatile(
        "mma.sync.aligned.m16n8k8.row.col.f32.tf32.tf32.f32 "
        "{%0,%1,%2,%3}, {%4,%5,%6,%7}, {%8,%9}, {%0,%1,%2,%3};\n"
        : "+f"(d[0]), "+f"(d[1]), "+f"(d[2]), "+f"(d[3])
        : "r"(a0), "r"(a1), "r"(a2), "r"(a3), "r"(b0), "r"(b1));
}

// ---------------------------------------------------------------------------
// Kernel 1: fused QKV projection. C = x @ W^T + b  (2304 x 1536, K=384)
// Block 128x64, Ktile 32, 8 warps (warp tile 32x32), tf32 mma.
// ---------------------------------------------------------------------------
__global__ __launch_bounds__(256) void qkv_mma(
    const float* __restrict__ x,
    const float* __restrict__ q_w, const float* __restrict__ q_b,
    const float* __restrict__ k_w, const float* __restrict__ k_b,
    const float* __restrict__ v_w, const float* __restrict__ v_b)
{
    __shared__ __align__(16) uint32_t sA[128 * 36];
    __shared__ __align__(16) uint32_t sB[64 * 36];

    const int tid  = threadIdx.x;
    const int warp = tid >> 5, lane = tid & 31;
    const int g = lane >> 2, t = lane & 3;
    const int warpM = warp & 3;
    const int warpN = warp >> 2;
    const int rowBase = blockIdx.x * 128;
    const int colBase = blockIdx.y * 64;

    const float* W; const float* bias; int sel, wBase;
    if (colBase < 256)      { W = q_w; bias = q_b; sel = 0; wBase = colBase;       }
    else if (colBase < 512) { W = k_w; bias = k_b; sel = 1; wBase = colBase - 256; }
    else                    { W = v_w; bias = v_b; sel = 2; wBase = colBase - 512; }

    float acc[2][4][4];
    #pragma unroll
    for (int mt = 0; mt < 2; mt++)
        #pragma unroll
        for (int nt = 0; nt < 4; nt++)
            #pragma unroll
            for (int j = 0; j < 4; j++) acc[mt][nt][j] = 0.f;

    for (int k0 = 0; k0 < DIMX; k0 += 32) {
        #pragma unroll
        for (int it = 0; it < 4; it++) {
            int i = tid + it * 256;
            int r = i >> 3, c = (i & 7) << 2;
            float4 a = *(const float4*)(x + (rowBase + r) * DIMX + k0 + c);
            uint4 u = {f2tf(a.x), f2tf(a.y), f2tf(a.z), f2tf(a.w)};
            *(uint4*)&sA[r * 36 + c] = u;
        }
        #pragma unroll
        for (int it = 0; it < 2; it++) {
            int i = tid + it * 256;
            int r = i >> 3, c = (i & 7) << 2;
            float4 b = *(const float4*)(W + (wBase + r) * DIMX + k0 + c);
            uint4 u = {f2tf(b.x), f2tf(b.y), f2tf(b.z), f2tf(b.w)};
            *(uint4*)&sB[r * 36 + c] = u;
        }
        __syncthreads();

        #pragma unroll
        for (int kk = 0; kk < 4; kk++) {
            uint32_t af[2][4], bf[4][2];
            #pragma unroll
            for (int mt = 0; mt < 2; mt++) {
                int row = warpM * 32 + mt * 16;
                af[mt][0] = sA[(row + g) * 36 + kk * 8 + t];
                af[mt][1] = sA[(row + 8 + g) * 36 + kk * 8 + t];
                af[mt][2] = sA[(row + g) * 36 + kk * 8 + t + 4];
                af[mt][3] = sA[(row + 8 + g) * 36 + kk * 8 + t + 4];
            }
            #pragma unroll
            for (int nt = 0; nt < 4; nt++) {
                int col = warpN * 32 + nt * 8;
                bf[nt][0] = sB[(col + g) * 36 + kk * 8 + t];
                bf[nt][1] = sB[(col + g) * 36 + kk * 8 + t + 4];
            }
            #pragma unroll
            for (int mt = 0; mt < 2; mt++)
                #pragma unroll
                for (int nt = 0; nt < 4; nt++)
                    mma8(acc[mt][nt], af[mt][0], af[mt][1], af[mt][2], af[mt][3],
                         bf[nt][0], bf[nt][1]);
        }
        __syncthreads();
    }

    #pragma unroll
    for (int nt = 0; nt < 4; nt++) {
        int jl = wBase + warpN * 32 + nt * 8 + 2 * t;
        float b0v = bias[jl], b1v = bias[jl + 1];
        #pragma unroll
        for (int mt = 0; mt < 2; mt++) {
            int row0 = rowBase + warpM * 32 + mt * 16 + g;
            int row1 = row0 + 8;
            float2 lo = {acc[mt][nt][0] + b0v, acc[mt][nt][1] + b1v};
            float2 hi = {acc[mt][nt][2] + b0v, acc[mt][nt][3] + b1v};
            if (sel == 0) {
                int h = jl >> 5, kd = jl & 31;
                *(float2*)&g_Q[(h * N_TOK + row0) * KD + kd] = lo;
                *(float2*)&g_Q[(h * N_TOK + row1) * KD + kd] = hi;
            } else if (sel == 1) {
                int h = jl >> 5, kd = jl & 31;
                *(float2*)&g_K[(h * N_TOK + row0) * KD + kd] = lo;
                *(float2*)&g_K[(h * N_TOK + row1) * KD + kd] = hi;
            } else {
                int h = jl >> 7, dv = jl & 127;
                *(float2*)&g_V[(h * N_TOK + row0) * DV + dv] = lo;
                *(float2*)&g_V[(h * N_TOK + row1) * DV + dv] = hi;
            }
        }
    }
}

// ---------------------------------------------------------------------------
// Kernel 2: flash attention, tf32 mma. BQ=128, BK=64, 512 threads (16 warps).
// warp = (rowGroup rg = warp>>1) x (colGroup cg = warp&1).
// Warp owns 16 query rows and 64 V columns. Softmax warp-local.
// P fragments produced by quad shuffles (no smem round trip).
// ---------------------------------------------------------------------------
#define AT_SK    0                      // 64*36  = 2304
#define AT_SV    (AT_SK + 64 * 36)      // 64*136 = 8704 (Q tile aliased here)
#define AT_SBIAS (AT_SV + 64 * 136)     // 2304
#define AT_TOTAL (AT_SBIAS + N_TOK)     // 13312 u32 = 53248 bytes

__global__ __launch_bounds__(512, 1) void attn_mma(
    const float* __restrict__ biases, const int* __restrict__ idxs)
{
    extern __shared__ __align__(16) uint32_t smu[];
    uint32_t* sK = smu + AT_SK;
    uint32_t* sV = smu + AT_SV;
    uint32_t* sQ = smu + AT_SV;          // alias: Q only lives in prologue
    float*    sBias = (float*)(smu + AT_SBIAS);

    const int tid  = threadIdx.x;
    const int warp = tid >> 5, lane = tid & 31;
    const int g = lane >> 2, t = lane & 3;
    const int rg = warp >> 1;            // row group 0..7
    const int cg = warp & 1;             // col group 0..1
    const int h  = blockIdx.y;
    const int q0 = blockIdx.x * 128;

    // --- prologue: Q tile -> smem (tf32, aliased into sV), bias -> smem ---
    {
        const float4* src = (const float4*)(g_Q + (h * N_TOK + q0) * KD);
        #pragma unroll
        for (int it = 0; it < 3; it++) {
            int i = tid + it * 512;
            if (i < 1152) {
                int r = i >> 3, c = (i & 7) << 2;
                float4 q = src[i];
                uint4 u = {f2tf(q.x), f2tf(q.y), f2tf(q.z), f2tf(q.w)};
                *(uint4*)&sQ[r * 36 + c] = u;
            }
        }
        #pragma unroll
        for (int it = 0; it < 5; it++) {
            int i = tid + it * 512;
            if (i < N_TOK) sBias[i] = biases[h * N_TOK + i];
        }
    }
    __syncthreads();

    // --- Q fragments, register resident ---
    uint32_t qf[4][4];
    {
        int row = 16 * rg + g;
        #pragma unroll
        for (int kk = 0; kk < 4; kk++) {
            qf[kk][0] = sQ[row * 36 + kk * 8 + t];
            qf[kk][1] = sQ[(row + 8) * 36 + kk * 8 + t];
            qf[kk][2] = sQ[row * 36 + kk * 8 + t + 4];
            qf[kk][3] = sQ[(row + 8) * 36 + kk * 8 + t + 4];
        }
    }

    float m0 = -1e30f, m1 = -1e30f, l0 = 0.f, l1 = 0.f;
    float o[8][4];
    #pragma unroll
    for (int vt = 0; vt < 8; vt++)
        #pragma unroll
        for (int j = 0; j < 4; j++) o[vt][j] = 0.f;

    const int rowW = 16 * rg + g;
    const int gRow0 = q0 + rowW;
    const int gRow1 = gRow0 + 8;
    const int vColBase = cg * 64;        // this warp's V column base
    const unsigned FULL = 0xffffffffu;
    const int srcA = (lane & ~3) | (t >> 1);
    const bool odd = (t & 1);

    for (int k0 = 0; k0 < N_TOK; k0 += 64) {
        __syncthreads();   // prior tile fully consumed (and qf reads done)
        // --- load K tile 64x32 (stride 36) ---
        {
            const float4* src = (const float4*)(g_K + (h * N_TOK + k0) * KD);
            int i = tid;
            int r = i >> 3, c = (i & 7) << 2;
            float4 k = src[i];
            uint4 u = {f2tf(k.x), f2tf(k.y), f2tf(k.z), f2tf(k.w)};
            *(uint4*)&sK[r * 36 + c] = u;
        }
        // --- load V tile 64x128 (stride 136) ---
        {
            const float4* src = (const float4*)(g_V + (h * N_TOK + k0) * DV);
            #pragma unroll
            for (int it = 0; it < 4; it++) {
                int i = tid + it * 512;
                int r = i >> 5, c = (i & 31) << 2;
                float4 v = src[i];
                uint4 u = {f2tf(v.x), f2tf(v.y), f2tf(v.z), f2tf(v.w)};
                *(uint4*)&sV[r * 136 + c] = u;
            }
        }
        __syncthreads();

        // --- S = Q @ K^T (16 rows x 64 cols) + scale + bias gather ---
        float sreg[8][4];
        #pragma unroll
        for (int nt = 0; nt < 8; nt++) {
            float s4[4] = {0.f, 0.f, 0.f, 0.f};
            #pragma unroll
            for (int kk = 0; kk < 4; kk++) {
                uint32_t b0 = sK[(nt * 8 + g) * 36 + kk * 8 + t];
                uint32_t b1 = sK[(nt * 8 + g) * 36 + kk * 8 + t + 4];
                mma8(s4, qf[kk][0], qf[kk][1], qf[kk][2], qf[kk][3], b0, b1);
            }
            int colg = k0 + nt * 8 + 2 * t;
            int2 id0 = *(const int2*)(idxs + (long)gRow0 * N_TOK + colg);
            int2 id1 = *(const int2*)(idxs + (long)gRow1 * N_TOK + colg);
            sreg[nt][0] = s4[0] * SCALE_F + sBias[id0.x];
            sreg[nt][1] = s4[1] * SCALE_F + sBias[id0.y];
            sreg[nt][2] = s4[2] * SCALE_F + sBias[id1.x];
            sreg[nt][3] = s4[3] * SCALE_F + sBias[id1.y];
        }

        // --- online softmax, warp-local ---
        float mx0 = m0, mx1 = m1;
        #pragma unroll
        for (int nt = 0; nt < 8; nt++) {
            mx0 = fmaxf(mx0, fmaxf(sreg[nt][0], sreg[nt][1]));
            mx1 = fmaxf(mx1, fmaxf(sreg[nt][2], sreg[nt][3]));
        }
        mx0 = fmaxf(mx0, __shfl_xor_sync(FULL, mx0, 1));
        mx0 = fmaxf(mx0, __shfl_xor_sync(FULL, mx0, 2));
        mx1 = fmaxf(mx1, __shfl_xor_sync(FULL, mx1, 1));
        mx1 = fmaxf(mx1, __shfl_xor_sync(FULL, mx1, 2));
        float a0 = __expf(m0 - mx0), a1 = __expf(m1 - mx1);
        float sum0 = 0.f, sum1 = 0.f;
        #pragma unroll
        for (int nt = 0; nt < 8; nt++) {
            sreg[nt][0] = __expf(sreg[nt][0] - mx0);
            sreg[nt][1] = __expf(sreg[nt][1] - mx0);
            sreg[nt][2] = __expf(sreg[nt][2] - mx1);
            sreg[nt][3] = __expf(sreg[nt][3] - mx1);
            sum0 += sreg[nt][0] + sreg[nt][1];
            sum1 += sreg[nt][2] + sreg[nt][3];
        }
        sum0 += __shfl_xor_sync(FULL, sum0, 1);
        sum0 += __shfl_xor_sync(FULL, sum0, 2);
        sum1 += __shfl_xor_sync(FULL, sum1, 1);
        sum1 += __shfl_xor_sync(FULL, sum1, 2);
        l0 = l0 * a0 + sum0; m0 = mx0;
        l1 = l1 * a1 + sum1; m1 = mx1;

        // rescale O
        #pragma unroll
        for (int vt = 0; vt < 8; vt++) {
            o[vt][0] *= a0; o[vt][1] *= a0;
            o[vt][2] *= a1; o[vt][3] *= a1;
        }

        // --- O += P @ V : P fragments via quad shuffles ---
        #pragma unroll
        for (int kk = 0; kk < 8; kk++) {
            float x0 = __shfl_sync(FULL, sreg[kk][0], srcA);
            float x1 = __shfl_sync(FULL, sreg[kk][1], srcA);
            float x2 = __shfl_sync(FULL, sreg[kk][2], srcA);
            float x3 = __shfl_sync(FULL, sreg[kk][3], srcA);
            float y0 = __shfl_sync(FULL, sreg[kk][0], srcA + 2);
            float y1 = __shfl_sync(FULL, sreg[kk][1], srcA + 2);
            float y2 = __shfl_sync(FULL, sreg[kk][2], srcA + 2);
            float y3 = __shfl_sync(FULL, sreg[kk][3], srcA + 2);
            uint32_t pa0 = f2tf(odd ? x1 : x0);   // (g,   t)
            uint32_t pa1 = f2tf(odd ? x3 : x2);   // (g+8, t)
            uint32_t pa2 = f2tf(odd ? y1 : y0);   // (g,   t+4)
            uint32_t pa3 = f2tf(odd ? y3 : y2);   // (g+8, t+4)
            #pragma unroll
            for (int vt = 0; vt < 8; vt++) {
                int col = vColBase + vt * 8 + g;
                uint32_t b0 = sV[(kk * 8 + t) * 136 + col];
                uint32_t b1 = sV[(kk * 8 + t + 4) * 136 + col];
                mma8(o[vt], pa0, pa1, pa2, pa3, b0, b1);
            }
        }
    }

    // --- finalize, write O ---
    float inv0 = 1.f / l0, inv1 = 1.f / l1;
    #pragma unroll
    for (int vt = 0; vt < 8; vt++) {
        int col = vColBase + vt * 8 + 2 * t;
        float2 lo = {o[vt][0] * inv0, o[vt][1] * inv0};
        float2 hi = {o[vt][2] * inv1, o[vt][3] * inv1};
        *(float2*)&g_O[(long)gRow0 * DH + h * DV + col] = lo;
        *(float2*)&g_O[(long)gRow1 * DH + h * DV + col] = hi;
    }
}

// ---------------------------------------------------------------------------
// Kernel 3: output projection. y = O @ proj_w^T + proj_b (2304 x 384, K=1024)
// ---------------------------------------------------------------------------
__global__ __launch_bounds__(256) void proj_mma(
    const float* __restrict__ Wp, const float* __restrict__ pb,
    float* __restrict__ out)
{
    __shared__ __align__(16) uint32_t sA[128 * 36];
    __shared__ __align__(16) uint32_t sB[64 * 36];

    const int tid  = threadIdx.x;
    const int warp = tid >> 5, lane = tid & 31;
    const int g = lane >> 2, t = lane & 3;
    const int warpM = warp & 3;
    const int warpN = warp >> 2;
    const int rowBase = blockIdx.x * 128;
    const int colBase = blockIdx.y * 64;

    float acc[2][4][4];
    #pragma unroll
    for (int mt = 0; mt < 2; mt++)
        #pragma unroll
        for (int nt = 0; nt < 4; nt++)
            #pragma unroll
            for (int j = 0; j < 4; j++) acc[mt][nt][j] = 0.f;

    for (int k0 = 0; k0 < DH; k0 += 32) {
        #pragma unroll
        for (int it = 0; it < 4; it++) {
            int i = tid + it * 256;
            int r = i >> 3, c = (i & 7) << 2;
            float4 a = *(const float4*)(g_O + (long)(rowBase + r) * DH + k0 + c);
            uint4 u = {f2tf(a.x), f2tf(a.y), f2tf(a.z), f2tf(a.w)};
            *(uint4*)&sA[r * 36 + c] = u;
        }
        #pragma unroll
        for (int it = 0; it < 2; it++) {
            int i = tid + it * 256;
            int r = i >> 3, c = (i & 7) << 2;
            float4 b = *(const float4*)(Wp + (long)(colBase + r) * DH + k0 + c);
            uint4 u = {f2tf(b.x), f2tf(b.y), f2tf(b.z), f2tf(b.w)};
            *(uint4*)&sB[r * 36 + c] = u;
        }
        __syncthreads();

        #pragma unroll
        for (int kk = 0; kk < 4; kk++) {
            uint32_t af[2][4], bf[4][2];
            #pragma unroll
            for (int mt = 0; mt < 2; mt++) {
                int row = warpM * 32 + mt * 16;
                af[mt][0] = sA[(row + g) * 36 + kk * 8 + t];
                af[mt][1] = sA[(row + 8 + g) * 36 + kk * 8 + t];
                af[mt][2] = sA[(row + g) * 36 + kk * 8 + t + 4];
                af[mt][3] = sA[(row + 8 + g) * 36 + kk * 8 + t + 4];
            }
            #pragma unroll
            for (int nt = 0; nt < 4; nt++) {
                int col = warpN * 32 + nt * 8;
                bf[nt][0] = sB[(col + g) * 36 + kk * 8 + t];
                bf[nt][1] = sB[(col + g) * 36 + kk * 8 + t + 4];
            }
            #pragma unroll
            for (int mt = 0; mt < 2; mt++)
                #pragma unroll
                for (int nt = 0; nt < 4; nt++)
                    mma8(acc[mt][nt], af[mt][0], af[mt][1], af[mt][2], af[mt][3],
                         bf[nt][0], bf[nt][1]);
        }
        __syncthreads();
    }

    #pragma unroll
    for (int nt = 0; nt < 4; nt++) {
        int col = colBase + warpN * 32 + nt * 8 + 2 * t;
        float b0v = pb[col], b1v = pb[col + 1];
        #pragma unroll
        for (int mt = 0; mt < 2; mt++) {
            int row0 = rowBase + warpM * 32 + mt * 16 + g;
            int row1 = row0 + 8;
            float2 lo = {acc[mt][nt][0] + b0v, acc[mt][nt][1] + b1v};
            float2 hi = {acc[mt][nt][2] + b0v, acc[mt][nt][3] + b1v};
            *(float2*)&out[row0 * DIMX + col] = lo;
            *(float2*)&out[row1 * DIMX + col] = hi;
        }
    }
}

// ---------------------------------------------------------------------------
extern "C" void kernel_launch(void* const* d_in, const int* in_sizes, int n_in,
                              void* d_out, int out_size)
{
    const float* x       = (const float*)d_in[0];
    const float* q_w     = (const float*)d_in[1];
    const float* q_b     = (const float*)d_in[2];
    const float* k_w     = (const float*)d_in[3];
    const float* k_b     = (const float*)d_in[4];
    const float* v_w     = (const float*)d_in[5];
    const float* v_b     = (const float*)d_in[6];
    const float* proj_w  = (const float*)d_in[7];
    const float* proj_b  = (const float*)d_in[8];
    const float* biases  = (const float*)d_in[9];
    const int*   idxs    = (const int*)d_in[10];
    float* out = (float*)d_out;

    qkv_mma<<<dim3(N_TOK / 128, 1536 / 64), 256>>>(x, q_w, q_b, k_w, k_b, v_w, v_b);

    const size_t smemBytes = AT_TOTAL * sizeof(uint32_t);
    cudaFuncSetAttribute(attn_mma, cudaFuncAttributeMaxDynamicSharedMemorySize,
                         (int)smemBytes);
    attn_mma<<<dim3(N_TOK / 128, NHEADS), 512, smemBytes>>>(biases, idxs);

    proj_mma<<<dim3(N_TOK / 128, DIMX / 64), 256>>>(proj_w, proj_b, out);
}

// round 4
// speedup vs baseline: 1.2216x; 1.2216x over previous
#include <cuda_runtime.h>
#include <cstdint>

#define N_TOK 2304
#define DIMX 384
#define NHEADS 8
#define KD 32
#define DV 128
#define DH 1024
#define RES 48
#define SCALE_F 0.17677669529663687f

// Scratch (allocation-free rule: __device__ globals)
__device__ float g_Q[NHEADS * N_TOK * KD];   // [h][n][32]
__device__ float g_K[NHEADS * N_TOK * KD];   // [h][n][32]
__device__ float g_V[NHEADS * N_TOK * DV];   // [h][n][128]
__device__ float g_O[N_TOK * DH];            // [n][h*128+d]

// ---------------------------------------------------------------------------
// helpers
// ---------------------------------------------------------------------------
__device__ __forceinline__ uint32_t f2tf(float f) {
    uint32_t u;
    asm("cvt.rna.tf32.f32 %0, %1;" : "=r"(u) : "f"(f));
    return u;
}

__device__ __forceinline__ void mma8(float* d,
                                     uint32_t a0, uint32_t a1, uint32_t a2, uint32_t a3,
                                     uint32_t b0, uint32_t b1)
{
    asm volatile(
        "mma.sync.aligned.m16n8k8.row.col.f32.tf32.tf32.f32 "
        "{%0,%1,%2,%3}, {%4,%5,%6,%7}, {%8,%9}, {%0,%1,%2,%3};\n"
        : "+f"(d[0]), "+f"(d[1]), "+f"(d[2]), "+f"(d[3])
        : "r"(a0), "r"(a1), "r"(a2), "r"(a3), "r"(b0), "r"(b1));
}

// ---------------------------------------------------------------------------
// Kernel 1: fused QKV projection. C = x @ W^T + b  (2304 x 1536, K=384)
// Block 128x64, Ktile 32, 8 warps (warp tile 32x32), tf32 mma.
// ---------------------------------------------------------------------------
__global__ __launch_bounds__(256) void qkv_mma(
    const float* __restrict__ x,
    const float* __restrict__ q_w, const float* __restrict__ q_b,
    const float* __restrict__ k_w, const float* __restrict__ k_b,
    const float* __restrict__ v_w, const float* __restrict__ v_b)
{
    __shared__ __align__(16) uint32_t sA[128 * 36];
    __shared__ __align__(16) uint32_t sB[64 * 36];

    const int tid  = threadIdx.x;
    const int warp = tid >> 5, lane = tid & 31;
    const int g = lane >> 2, t = lane & 3;
    const int warpM = warp & 3;
    const int warpN = warp >> 2;
    const int rowBase = blockIdx.x * 128;
    const int colBase = blockIdx.y * 64;

    const float* W; const float* bias; int sel, wBase;
    if (colBase < 256)      { W = q_w; bias = q_b; sel = 0; wBase = colBase;       }
    else if (colBase < 512) { W = k_w; bias = k_b; sel = 1; wBase = colBase - 256; }
    else                    { W = v_w; bias = v_b; sel = 2; wBase = colBase - 512; }

    float acc[2][4][4];
    #pragma unroll
    for (int mt = 0; mt < 2; mt++)
        #pragma unroll
        for (int nt = 0; nt < 4; nt++)
            #pragma unroll
            for (int j = 0; j < 4; j++) acc[mt][nt][j] = 0.f;

    for (int k0 = 0; k0 < DIMX; k0 += 32) {
        #pragma unroll
        for (int it = 0; it < 4; it++) {
            int i = tid + it * 256;
            int r = i >> 3, c = (i & 7) << 2;
            float4 a = *(const float4*)(x + (rowBase + r) * DIMX + k0 + c);
            uint4 u = {f2tf(a.x), f2tf(a.y), f2tf(a.z), f2tf(a.w)};
            *(uint4*)&sA[r * 36 + c] = u;
        }
        #pragma unroll
        for (int it = 0; it < 2; it++) {
            int i = tid + it * 256;
            int r = i >> 3, c = (i & 7) << 2;
            float4 b = *(const float4*)(W + (wBase + r) * DIMX + k0 + c);
            uint4 u = {f2tf(b.x), f2tf(b.y), f2tf(b.z), f2tf(b.w)};
            *(uint4*)&sB[r * 36 + c] = u;
        }
        __syncthreads();

        #pragma unroll
        for (int kk = 0; kk < 4; kk++) {
            uint32_t af[2][4], bf[4][2];
            #pragma unroll
            for (int mt = 0; mt < 2; mt++) {
                int row = warpM * 32 + mt * 16;
                af[mt][0] = sA[(row + g) * 36 + kk * 8 + t];
                af[mt][1] = sA[(row + 8 + g) * 36 + kk * 8 + t];
                af[mt][2] = sA[(row + g) * 36 + kk * 8 + t + 4];
                af[mt][3] = sA[(row + 8 + g) * 36 + kk * 8 + t + 4];
            }
            #pragma unroll
            for (int nt = 0; nt < 4; nt++) {
                int col = warpN * 32 + nt * 8;
                bf[nt][0] = sB[(col + g) * 36 + kk * 8 + t];
                bf[nt][1] = sB[(col + g) * 36 + kk * 8 + t + 4];
            }
            #pragma unroll
            for (int mt = 0; mt < 2; mt++)
                #pragma unroll
                for (int nt = 0; nt < 4; nt++)
                    mma8(acc[mt][nt], af[mt][0], af[mt][1], af[mt][2], af[mt][3],
                         bf[nt][0], bf[nt][1]);
        }
        __syncthreads();
    }

    #pragma unroll
    for (int nt = 0; nt < 4; nt++) {
        int jl = wBase + warpN * 32 + nt * 8 + 2 * t;
        float b0v = bias[jl], b1v = bias[jl + 1];
        #pragma unroll
        for (int mt = 0; mt < 2; mt++) {
            int row0 = rowBase + warpM * 32 + mt * 16 + g;
            int row1 = row0 + 8;
            float2 lo = {acc[mt][nt][0] + b0v, acc[mt][nt][1] + b1v};
            float2 hi = {acc[mt][nt][2] + b0v, acc[mt][nt][3] + b1v};
            if (sel == 0) {
                int h = jl >> 5, kd = jl & 31;
                *(float2*)&g_Q[(h * N_TOK + row0) * KD + kd] = lo;
                *(float2*)&g_Q[(h * N_TOK + row1) * KD + kd] = hi;
            } else if (sel == 1) {
                int h = jl >> 5, kd = jl & 31;
                *(float2*)&g_K[(h * N_TOK + row0) * KD + kd] = lo;
                *(float2*)&g_K[(h * N_TOK + row1) * KD + kd] = hi;
            } else {
                int h = jl >> 7, dv = jl & 127;
                *(float2*)&g_V[(h * N_TOK + row0) * DV + dv] = lo;
                *(float2*)&g_V[(h * N_TOK + row1) * DV + dv] = hi;
            }
        }
    }
}

// ---------------------------------------------------------------------------
// Kernel 2: flash attention, tf32 mma. BQ=128, BK=64, 8 warps (R2 structure).
// Warp w owns query rows 16w..16w+15 -> warp-local softmax.
// Bias index computed arithmetically: idx = |y_n - y_m|*48 + |x_n - x_m|.
// NO idxs global loads at all.
// ---------------------------------------------------------------------------
#define AT_SQ    0                      // 128*36 = 4608
#define AT_SK    (AT_SQ + 128 * 36)     // 64*36  = 2304
#define AT_SV    (AT_SK + 64 * 36)      // 64*136 = 8704
#define AT_SS    (AT_SV + 64 * 136)     // 128*68 = 8704
#define AT_SBIAS (AT_SS + 128 * 68)     // 2304
#define AT_TOTAL (AT_SBIAS + N_TOK)     // 26624 u32 = 106496 bytes

__global__ __launch_bounds__(256, 1) void attn_mma(
    const float* __restrict__ biases)
{
    extern __shared__ __align__(16) uint32_t smu[];
    uint32_t* sQ = smu + AT_SQ;
    uint32_t* sK = smu + AT_SK;
    uint32_t* sV = smu + AT_SV;
    uint32_t* sS = smu + AT_SS;
    float*    sBias = (float*)(smu + AT_SBIAS);

    const int tid  = threadIdx.x;
    const int warp = tid >> 5, lane = tid & 31;
    const int g = lane >> 2, t = lane & 3;
    const int h  = blockIdx.y;
    const int q0 = blockIdx.x * 128;

    // --- prologue: Q tile -> smem (tf32), bias row -> smem ---
    {
        const float4* src = (const float4*)(g_Q + (h * N_TOK + q0) * KD);
        #pragma unroll
        for (int it = 0; it < 4; it++) {
            int i = tid + it * 256;
            int r = i >> 3, c = (i & 7) << 2;
            float4 q = src[i];
            uint4 u = {f2tf(q.x), f2tf(q.y), f2tf(q.z), f2tf(q.w)};
            *(uint4*)&sQ[r * 36 + c] = u;
        }
        #pragma unroll
        for (int it = 0; it < 9; it++)
            sBias[tid + it * 256] = biases[h * N_TOK + tid + it * 256];
    }
    __syncthreads();

    // --- Q fragments, register resident: qf[kstep][4] ---
    uint32_t qf[4][4];
    {
        int row = 16 * warp + g;
        #pragma unroll
        for (int kk = 0; kk < 4; kk++) {
            qf[kk][0] = sQ[row * 36 + kk * 8 + t];
            qf[kk][1] = sQ[(row + 8) * 36 + kk * 8 + t];
            qf[kk][2] = sQ[row * 36 + kk * 8 + t + 4];
            qf[kk][3] = sQ[(row + 8) * 36 + kk * 8 + t + 4];
        }
    }

    float m0 = -1e30f, m1 = -1e30f, l0 = 0.f, l1 = 0.f;
    float o[16][4];
    #pragma unroll
    for (int vt = 0; vt < 16; vt++)
        #pragma unroll
        for (int j = 0; j < 4; j++) o[vt][j] = 0.f;

    const int rowW = 16 * warp + g;           // this thread's row0 within tile
    const int gRow0 = q0 + rowW;              // global query row 0
    const int gRow1 = gRow0 + 8;              // global query row 1
    // query (y,x) coordinates for the two owned rows
    const int qy0 = gRow0 / RES, qx0 = gRow0 - qy0 * RES;
    const int qy1 = gRow1 / RES, qx1 = gRow1 - qy1 * RES;

    for (int k0 = 0; k0 < N_TOK; k0 += 64) {
        __syncthreads();   // previous iteration's sK/sV fully consumed
        // --- load K tile 64x32 (stride 36) ---
        {
            const float4* src = (const float4*)(g_K + (h * N_TOK + k0) * KD);
            #pragma unroll
            for (int it = 0; it < 2; it++) {
                int i = tid + it * 256;
                int r = i >> 3, c = (i & 7) << 2;
                float4 k = src[i];
                uint4 u = {f2tf(k.x), f2tf(k.y), f2tf(k.z), f2tf(k.w)};
                *(uint4*)&sK[r * 36 + c] = u;
            }
        }
        // --- load V tile 64x128 (stride 136) ---
        {
            const float4* src = (const float4*)(g_V + (h * N_TOK + k0) * DV);
            #pragma unroll
            for (int it = 0; it < 8; it++) {
                int i = tid + it * 256;
                int r = i >> 5, c = (i & 31) << 2;
                float4 v = src[i];
                uint4 u = {f2tf(v.x), f2tf(v.y), f2tf(v.z), f2tf(v.w)};
                *(uint4*)&sV[r * 136 + c] = u;
            }
        }
        __syncthreads();

        // --- S = Q @ K^T (warp rows x 64) + scale + computed bias ---
        float sreg[8][4];
        #pragma unroll
        for (int nt = 0; nt < 8; nt++) {
            float s4[4] = {0.f, 0.f, 0.f, 0.f};
            #pragma unroll
            for (int kk = 0; kk < 4; kk++) {
                uint32_t b0 = sK[(nt * 8 + g) * 36 + kk * 8 + t];
                uint32_t b1 = sK[(nt * 8 + g) * 36 + kk * 8 + t + 4];
                mma8(s4, qf[kk][0], qf[kk][1], qf[kk][2], qf[kk][3], b0, b1);
            }
            // key columns handled by this thread: colg, colg+1
            int c0 = k0 + nt * 8 + 2 * t;
            int c1 = c0 + 1;
            int ky0 = c0 / RES, kx0 = c0 - ky0 * RES;
            int ky1 = c1 / RES, kx1 = c1 - ky1 * RES;
            sreg[nt][0] = s4[0] * SCALE_F + sBias[abs(qy0 - ky0) * RES + abs(qx0 - kx0)];
            sreg[nt][1] = s4[1] * SCALE_F + sBias[abs(qy0 - ky1) * RES + abs(qx0 - kx1)];
            sreg[nt][2] = s4[2] * SCALE_F + sBias[abs(qy1 - ky0) * RES + abs(qx1 - kx0)];
            sreg[nt][3] = s4[3] * SCALE_F + sBias[abs(qy1 - ky1) * RES + abs(qx1 - kx1)];
        }

        // --- online softmax, warp-local (quad reduction) ---
        float mx0 = m0, mx1 = m1;
        #pragma unroll
        for (int nt = 0; nt < 8; nt++) {
            mx0 = fmaxf(mx0, fmaxf(sreg[nt][0], sreg[nt][1]));
            mx1 = fmaxf(mx1, fmaxf(sreg[nt][2], sreg[nt][3]));
        }
        mx0 = fmaxf(mx0, __shfl_xor_sync(0xffffffffu, mx0, 1));
        mx0 = fmaxf(mx0, __shfl_xor_sync(0xffffffffu, mx0, 2));
        mx1 = fmaxf(mx1, __shfl_xor_sync(0xffffffffu, mx1, 1));
        mx1 = fmaxf(mx1, __shfl_xor_sync(0xffffffffu, mx1, 2));
        float a0 = __expf(m0 - mx0), a1 = __expf(m1 - mx1);
        float sum0 = 0.f, sum1 = 0.f;
        #pragma unroll
        for (int nt = 0; nt < 8; nt++) {
            float p0 = __expf(sreg[nt][0] - mx0);
            float p1 = __expf(sreg[nt][1] - mx0);
            float p2 = __expf(sreg[nt][2] - mx1);
            float p3 = __expf(sreg[nt][3] - mx1);
            sum0 += p0 + p1; sum1 += p2 + p3;
            uint2 u0 = {f2tf(p0), f2tf(p1)};
            uint2 u1 = {f2tf(p2), f2tf(p3)};
            *(uint2*)&sS[rowW * 68 + nt * 8 + 2 * t] = u0;
            *(uint2*)&sS[(rowW + 8) * 68 + nt * 8 + 2 * t] = u1;
        }
        sum0 += __shfl_xor_sync(0xffffffffu, sum0, 1);
        sum0 += __shfl_xor_sync(0xffffffffu, sum0, 2);
        sum1 += __shfl_xor_sync(0xffffffffu, sum1, 1);
        sum1 += __shfl_xor_sync(0xffffffffu, sum1, 2);
        l0 = l0 * a0 + sum0; m0 = mx0;
        l1 = l1 * a1 + sum1; m1 = mx1;

        // rescale O
        #pragma unroll
        for (int vt = 0; vt < 16; vt++) {
            o[vt][0] *= a0; o[vt][1] *= a0;
            o[vt][2] *= a1; o[vt][3] *= a1;
        }
        __syncwarp();

        // --- O += P @ V ---
        #pragma unroll
        for (int kk = 0; kk < 8; kk++) {
            uint32_t p0 = sS[rowW * 68 + kk * 8 + t];
            uint32_t p1 = sS[(rowW + 8) * 68 + kk * 8 + t];
            uint32_t p2 = sS[rowW * 68 + kk * 8 + t + 4];
            uint32_t p3 = sS[(rowW + 8) * 68 + kk * 8 + t + 4];
            #pragma unroll
            for (int vt = 0; vt < 16; vt++) {
                uint32_t b0 = sV[(kk * 8 + t) * 136 + vt * 8 + g];
                uint32_t b1 = sV[(kk * 8 + t + 4) * 136 + vt * 8 + g];
                mma8(o[vt], p0, p1, p2, p3, b0, b1);
            }
        }
    }

    // --- finalize, write O ---
    float inv0 = 1.f / l0, inv1 = 1.f / l1;
    #pragma unroll
    for (int vt = 0; vt < 16; vt++) {
        int col = vt * 8 + 2 * t;
        float2 lo = {o[vt][0] * inv0, o[vt][1] * inv0};
        float2 hi = {o[vt][2] * inv1, o[vt][3] * inv1};
        *(float2*)&g_O[(long)gRow0 * DH + h * DV + col] = lo;
        *(float2*)&g_O[(long)gRow1 * DH + h * DV + col] = hi;
    }
}

// ---------------------------------------------------------------------------
// Kernel 3: output projection. y = O @ proj_w^T + proj_b (2304 x 384, K=1024)
// ---------------------------------------------------------------------------
__global__ __launch_bounds__(256) void proj_mma(
    const float* __restrict__ Wp, const float* __restrict__ pb,
    float* __restrict__ out)
{
    __shared__ __align__(16) uint32_t sA[128 * 36];
    __shared__ __align__(16) uint32_t sB[64 * 36];

    const int tid  = threadIdx.x;
    const int warp = tid >> 5, lane = tid & 31;
    const int g = lane >> 2, t = lane & 3;
    const int warpM = warp & 3;
    const int warpN = warp >> 2;
    const int rowBase = blockIdx.x * 128;
    const int colBase = blockIdx.y * 64;

    float acc[2][4][4];
    #pragma unroll
    for (int mt = 0; mt < 2; mt++)
        #pragma unroll
        for (int nt = 0; nt < 4; nt++)
            #pragma unroll
            for (int j = 0; j < 4; j++) acc[mt][nt][j] = 0.f;

    for (int k0 = 0; k0 < DH; k0 += 32) {
        #pragma unroll
        for (int it = 0; it < 4; it++) {
            int i = tid + it * 256;
            int r = i >> 3, c = (i & 7) << 2;
            float4 a = *(const float4*)(g_O + (long)(rowBase + r) * DH + k0 + c);
            uint4 u = {f2tf(a.x), f2tf(a.y), f2tf(a.z), f2tf(a.w)};
            *(uint4*)&sA[r * 36 + c] = u;
        }
        #pragma unroll
        for (int it = 0; it < 2; it++) {
            int i = tid + it * 256;
            int r = i >> 3, c = (i & 7) << 2;
            float4 b = *(const float4*)(Wp + (long)(colBase + r) * DH + k0 + c);
            uint4 u = {f2tf(b.x), f2tf(b.y), f2tf(b.z), f2tf(b.w)};
            *(uint4*)&sB[r * 36 + c] = u;
        }
        __syncthreads();

        #pragma unroll
        for (int kk = 0; kk < 4; kk++) {
            uint32_t af[2][4], bf[4][2];
            #pragma unroll
            for (int mt = 0; mt < 2; mt++) {
                int row = warpM * 32 + mt * 16;
                af[mt][0] = sA[(row + g) * 36 + kk * 8 + t];
                af[mt][1] = sA[(row + 8 + g) * 36 + kk * 8 + t];
                af[mt][2] = sA[(row + g) * 36 + kk * 8 + t + 4];
                af[mt][3] = sA[(row + 8 + g) * 36 + kk * 8 + t + 4];
            }
            #pragma unroll
            for (int nt = 0; nt < 4; nt++) {
                int col = warpN * 32 + nt * 8;
                bf[nt][0] = sB[(col + g) * 36 + kk * 8 + t];
                bf[nt][1] = sB[(col + g) * 36 + kk * 8 + t + 4];
            }
            #pragma unroll
            for (int mt = 0; mt < 2; mt++)
                #pragma unroll
                for (int nt = 0; nt < 4; nt++)
                    mma8(acc[mt][nt], af[mt][0], af[mt][1], af[mt][2], af[mt][3],
                         bf[nt][0], bf[nt][1]);
        }
        __syncthreads();
    }

    #pragma unroll
    for (int nt = 0; nt < 4; nt++) {
        int col = colBase + warpN * 32 + nt * 8 + 2 * t;
        float b0v = pb[col], b1v = pb[col + 1];
        #pragma unroll
        for (int mt = 0; mt < 2; mt++) {
            int row0 = rowBase + warpM * 32 + mt * 16 + g;
            int row1 = row0 + 8;
            float2 lo = {acc[mt][nt][0] + b0v, acc[mt][nt][1] + b1v};
            float2 hi = {acc[mt][nt][2] + b0v, acc[mt][nt][3] + b1v};
            *(float2*)&out[row0 * DIMX + col] = lo;
            *(float2*)&out[row1 * DIMX + col] = hi;
        }
    }
}

// ---------------------------------------------------------------------------
extern "C" void kernel_launch(void* const* d_in, const int* in_sizes, int n_in,
                              void* d_out, int out_size)
{
    const float* x       = (const float*)d_in[0];
    const float* q_w     = (const float*)d_in[1];
    const float* q_b     = (const float*)d_in[2];
    const float* k_w     = (const float*)d_in[3];
    const float* k_b     = (const float*)d_in[4];
    const float* v_w     = (const float*)d_in[5];
    const float* v_b     = (const float*)d_in[6];
    const float* proj_w  = (const float*)d_in[7];
    const float* proj_b  = (const float*)d_in[8];
    const float* biases  = (const float*)d_in[9];
    float* out = (float*)d_out;

    qkv_mma<<<dim3(N_TOK / 128, 1536 / 64), 256>>>(x, q_w, q_b, k_w, k_b, v_w, v_b);

    const size_t smemBytes = AT_TOTAL * sizeof(uint32_t);
    cudaFuncSetAttribute(attn_mma, cudaFuncAttributeMaxDynamicSharedMemorySize,
                         (int)smemBytes);
    attn_mma<<<dim3(N_TOK / 128, NHEADS), 256, smemBytes>>>(biases);

    proj_mma<<<dim3(N_TOK / 128, DIMX / 64), 256>>>(proj_w, proj_b, out);
}

// round 5
// speedup vs baseline: 1.3230x; 1.0830x over previous
#include <cuda_runtime.h>
#include <cstdint>

#define N_TOK 2304
#define DIMX 384
#define NHEADS 8
#define KD 32
#define DV 128
#define DH 1024
#define RES 48
#define SCALE_F 0.17677669529663687f

// Scratch (allocation-free rule: __device__ globals)
// NOTE: g_Q/g_K/g_V hold tf32-rounded bit patterns (written by qkv epilogue).
__device__ float g_Q[NHEADS * N_TOK * KD];   // [h][n][32]
__device__ float g_K[NHEADS * N_TOK * KD];   // [h][n][32]
__device__ float g_V[NHEADS * N_TOK * DV];   // [h][n][128]
__device__ float g_O[N_TOK * DH];            // [n][h*128+d] (fp32)

// ---------------------------------------------------------------------------
// helpers
// ---------------------------------------------------------------------------
__device__ __forceinline__ uint32_t f2tf(float f) {
    uint32_t u;
    asm("cvt.rna.tf32.f32 %0, %1;" : "=r"(u) : "f"(f));
    return u;
}

__device__ __forceinline__ void mma8(float* d,
                                     uint32_t a0, uint32_t a1, uint32_t a2, uint32_t a3,
                                     uint32_t b0, uint32_t b1)
{
    asm volatile(
        "mma.sync.aligned.m16n8k8.row.col.f32.tf32.tf32.f32 "
        "{%0,%1,%2,%3}, {%4,%5,%6,%7}, {%8,%9}, {%0,%1,%2,%3};\n"
        : "+f"(d[0]), "+f"(d[1]), "+f"(d[2]), "+f"(d[3])
        : "r"(a0), "r"(a1), "r"(a2), "r"(a3), "r"(b0), "r"(b1));
}

__device__ __forceinline__ void cp16(uint32_t* smem_dst, const void* gsrc) {
    uint32_t sa = (uint32_t)__cvta_generic_to_shared(smem_dst);
    asm volatile("cp.async.cg.shared.global [%0], [%1], 16;\n" :: "r"(sa), "l"(gsrc));
}
__device__ __forceinline__ void cp_commit() {
    asm volatile("cp.async.commit_group;\n");
}
template <int N>
__device__ __forceinline__ void cp_wait() {
    asm volatile("cp.async.wait_group %0;\n" :: "n"(N));
}

// ---------------------------------------------------------------------------
// Kernel 1: fused QKV projection. C = x @ W^T + b  (2304 x 1536, K=384)
// Block 128x64, Ktile 32, 8 warps (warp tile 32x32), tf32 mma.
// Epilogue stores tf32-rounded bits into g_Q/g_K/g_V.
// ---------------------------------------------------------------------------
__global__ __launch_bounds__(256) void qkv_mma(
    const float* __restrict__ x,
    const float* __restrict__ q_w, const float* __restrict__ q_b,
    const float* __restrict__ k_w, const float* __restrict__ k_b,
    const float* __restrict__ v_w, const float* __restrict__ v_b)
{
    __shared__ __align__(16) uint32_t sA[128 * 36];
    __shared__ __align__(16) uint32_t sB[64 * 36];

    const int tid  = threadIdx.x;
    const int warp = tid >> 5, lane = tid & 31;
    const int g = lane >> 2, t = lane & 3;
    const int warpM = warp & 3;
    const int warpN = warp >> 2;
    const int rowBase = blockIdx.x * 128;
    const int colBase = blockIdx.y * 64;

    const float* W; const float* bias; int sel, wBase;
    if (colBase < 256)      { W = q_w; bias = q_b; sel = 0; wBase = colBase;       }
    else if (colBase < 512) { W = k_w; bias = k_b; sel = 1; wBase = colBase - 256; }
    else                    { W = v_w; bias = v_b; sel = 2; wBase = colBase - 512; }

    float acc[2][4][4];
    #pragma unroll
    for (int mt = 0; mt < 2; mt++)
        #pragma unroll
        for (int nt = 0; nt < 4; nt++)
            #pragma unroll
            for (int j = 0; j < 4; j++) acc[mt][nt][j] = 0.f;

    for (int k0 = 0; k0 < DIMX; k0 += 32) {
        #pragma unroll
        for (int it = 0; it < 4; it++) {
            int i = tid + it * 256;
            int r = i >> 3, c = (i & 7) << 2;
            float4 a = *(const float4*)(x + (rowBase + r) * DIMX + k0 + c);
            uint4 u = {f2tf(a.x), f2tf(a.y), f2tf(a.z), f2tf(a.w)};
            *(uint4*)&sA[r * 36 + c] = u;
        }
        #pragma unroll
        for (int it = 0; it < 2; it++) {
            int i = tid + it * 256;
            int r = i >> 3, c = (i & 7) << 2;
            float4 b = *(const float4*)(W + (wBase + r) * DIMX + k0 + c);
            uint4 u = {f2tf(b.x), f2tf(b.y), f2tf(b.z), f2tf(b.w)};
            *(uint4*)&sB[r * 36 + c] = u;
        }
        __syncthreads();

        #pragma unroll
        for (int kk = 0; kk < 4; kk++) {
            uint32_t af[2][4], bf[4][2];
            #pragma unroll
            for (int mt = 0; mt < 2; mt++) {
                int row = warpM * 32 + mt * 16;
                af[mt][0] = sA[(row + g) * 36 + kk * 8 + t];
                af[mt][1] = sA[(row + 8 + g) * 36 + kk * 8 + t];
                af[mt][2] = sA[(row + g) * 36 + kk * 8 + t + 4];
                af[mt][3] = sA[(row + 8 + g) * 36 + kk * 8 + t + 4];
            }
            #pragma unroll
            for (int nt = 0; nt < 4; nt++) {
                int col = warpN * 32 + nt * 8;
                bf[nt][0] = sB[(col + g) * 36 + kk * 8 + t];
                bf[nt][1] = sB[(col + g) * 36 + kk * 8 + t + 4];
            }
            #pragma unroll
            for (int mt = 0; mt < 2; mt++)
                #pragma unroll
                for (int nt = 0; nt < 4; nt++)
                    mma8(acc[mt][nt], af[mt][0], af[mt][1], af[mt][2], af[mt][3],
                         bf[nt][0], bf[nt][1]);
        }
        __syncthreads();
    }

    // epilogue: bias, then tf32-round and store bit patterns
    #pragma unroll
    for (int nt = 0; nt < 4; nt++) {
        int jl = wBase + warpN * 32 + nt * 8 + 2 * t;
        float b0v = bias[jl], b1v = bias[jl + 1];
        #pragma unroll
        for (int mt = 0; mt < 2; mt++) {
            int row0 = rowBase + warpM * 32 + mt * 16 + g;
            int row1 = row0 + 8;
            float2 lo = {__uint_as_float(f2tf(acc[mt][nt][0] + b0v)),
                         __uint_as_float(f2tf(acc[mt][nt][1] + b1v))};
            float2 hi = {__uint_as_float(f2tf(acc[mt][nt][2] + b0v)),
                         __uint_as_float(f2tf(acc[mt][nt][3] + b1v))};
            if (sel == 0) {
                int h = jl >> 5, kd = jl & 31;
                *(float2*)&g_Q[(h * N_TOK + row0) * KD + kd] = lo;
                *(float2*)&g_Q[(h * N_TOK + row1) * KD + kd] = hi;
            } else if (sel == 1) {
                int h = jl >> 5, kd = jl & 31;
                *(float2*)&g_K[(h * N_TOK + row0) * KD + kd] = lo;
                *(float2*)&g_K[(h * N_TOK + row1) * KD + kd] = hi;
            } else {
                int h = jl >> 7, dv = jl & 127;
                *(float2*)&g_V[(h * N_TOK + row0) * DV + dv] = lo;
                *(float2*)&g_V[(h * N_TOK + row1) * DV + dv] = hi;
            }
        }
    }
}

// ---------------------------------------------------------------------------
// Kernel 2: flash attention, tf32 mma. BQ=128, BK=64, 8 warps.
// Double-buffered K/V mainloop via cp.async (tiles are pre-converted tf32 bits).
// Bias index computed arithmetically: idx = |dy|*48 + |dx| (no idxs loads).
// ---------------------------------------------------------------------------
#define KBUF (64 * 36)                   // 2304 u32 per K buffer
#define VBUF (64 * 136)                  // 8704 u32 per V buffer
#define AT_SQ    0                       // 128*36 = 4608
#define AT_SK    (AT_SQ + 128 * 36)      // 2 x 2304
#define AT_SV    (AT_SK + 2 * KBUF)      // 2 x 8704
#define AT_SS    (AT_SV + 2 * VBUF)      // 128*68 = 8704
#define AT_SBIAS (AT_SS + 128 * 68)      // 2304
#define AT_TOTAL (AT_SBIAS + N_TOK)      // 37632 u32 = 150528 bytes

__global__ __launch_bounds__(256, 1) void attn_mma(
    const float* __restrict__ biases)
{
    extern __shared__ __align__(16) uint32_t smu[];
    uint32_t* sQ = smu + AT_SQ;
    uint32_t* sKb = smu + AT_SK;
    uint32_t* sVb = smu + AT_SV;
    uint32_t* sS = smu + AT_SS;
    float*    sBias = (float*)(smu + AT_SBIAS);

    const int tid  = threadIdx.x;
    const int warp = tid >> 5, lane = tid & 31;
    const int g = lane >> 2, t = lane & 3;
    const int h  = blockIdx.y;
    const int q0 = blockIdx.x * 128;

    const uint32_t* gK = (const uint32_t*)(g_K + h * N_TOK * KD);
    const uint32_t* gV = (const uint32_t*)(g_V + h * N_TOK * DV);

    // --- prologue: Q tile (already tf32 bits) -> smem, bias row -> smem ---
    {
        const uint4* src = (const uint4*)(g_Q + (h * N_TOK + q0) * KD);
        #pragma unroll
        for (int it = 0; it < 4; it++) {
            int i = tid + it * 256;
            int r = i >> 3, c = (i & 7) << 2;
            *(uint4*)&sQ[r * 36 + c] = src[i];
        }
        #pragma unroll
        for (int it = 0; it < 9; it++)
            sBias[tid + it * 256] = biases[h * N_TOK + tid + it * 256];
    }

    // --- prefetch tile 0 into buffer 0 ---
    {
        #pragma unroll
        for (int it = 0; it < 2; it++) {
            int i = tid + it * 256;
            int r = i >> 3, c = (i & 7) << 2;
            cp16(&sKb[r * 36 + c], gK + i * 4);
        }
        #pragma unroll
        for (int it = 0; it < 8; it++) {
            int i = tid + it * 256;
            int r = i >> 5, c = (i & 31) << 2;
            cp16(&sVb[r * 136 + c], gV + i * 4);
        }
        cp_commit();
    }
    __syncthreads();   // sQ visible

    // --- Q fragments, register resident: qf[kstep][4] ---
    uint32_t qf[4][4];
    {
        int row = 16 * warp + g;
        #pragma unroll
        for (int kk = 0; kk < 4; kk++) {
            qf[kk][0] = sQ[row * 36 + kk * 8 + t];
            qf[kk][1] = sQ[(row + 8) * 36 + kk * 8 + t];
            qf[kk][2] = sQ[row * 36 + kk * 8 + t + 4];
            qf[kk][3] = sQ[(row + 8) * 36 + kk * 8 + t + 4];
        }
    }

    float m0 = -1e30f, m1 = -1e30f, l0 = 0.f, l1 = 0.f;
    float o[16][4];
    #pragma unroll
    for (int vt = 0; vt < 16; vt++)
        #pragma unroll
        for (int j = 0; j < 4; j++) o[vt][j] = 0.f;

    const int rowW = 16 * warp + g;
    const int gRow0 = q0 + rowW;
    const int gRow1 = gRow0 + 8;
    const int qy0 = gRow0 / RES, qx0 = gRow0 - qy0 * RES;
    const int qy1 = gRow1 / RES, qx1 = gRow1 - qy1 * RES;

    const int NITER = N_TOK / 64;   // 36

    for (int ki = 0; ki < NITER; ki++) {
        const int cur = ki & 1, nxt = cur ^ 1;
        // --- prefetch tile ki+1 into the other buffer ---
        if (ki + 1 < NITER) {
            const uint32_t* gKn = gK + (ki + 1) * 64 * KD;
            const uint32_t* gVn = gV + (ki + 1) * 64 * DV;
            #pragma unroll
            for (int it = 0; it < 2; it++) {
                int i = tid + it * 256;
                int r = i >> 3, c = (i & 7) << 2;
                cp16(&sKb[nxt * KBUF + r * 36 + c], gKn + i * 4);
            }
            #pragma unroll
            for (int it = 0; it < 8; it++) {
                int i = tid + it * 256;
                int r = i >> 5, c = (i & 31) << 2;
                cp16(&sVb[nxt * VBUF + r * 136 + c], gVn + i * 4);
            }
            cp_commit();
            cp_wait<1>();     // tile ki landed; ki+1 still in flight
        } else {
            cp_wait<0>();     // last tile: drain everything
        }
        __syncthreads();

        const uint32_t* sK = sKb + cur * KBUF;
        const uint32_t* sV = sVb + cur * VBUF;
        const int k0 = ki * 64;

        // --- S = Q @ K^T (warp rows x 64) + scale + computed bias ---
        float sreg[8][4];
        #pragma unroll
        for (int nt = 0; nt < 8; nt++) {
            float s4[4] = {0.f, 0.f, 0.f, 0.f};
            #pragma unroll
            for (int kk = 0; kk < 4; kk++) {
                uint32_t b0 = sK[(nt * 8 + g) * 36 + kk * 8 + t];
                uint32_t b1 = sK[(nt * 8 + g) * 36 + kk * 8 + t + 4];
                mma8(s4, qf[kk][0], qf[kk][1], qf[kk][2], qf[kk][3], b0, b1);
            }
            int c0 = k0 + nt * 8 + 2 * t;
            int c1 = c0 + 1;
            int ky0 = c0 / RES, kx0 = c0 - ky0 * RES;
            int ky1 = c1 / RES, kx1 = c1 - ky1 * RES;
            sreg[nt][0] = s4[0] * SCALE_F + sBias[abs(qy0 - ky0) * RES + abs(qx0 - kx0)];
            sreg[nt][1] = s4[1] * SCALE_F + sBias[abs(qy0 - ky1) * RES + abs(qx0 - kx1)];
            sreg[nt][2] = s4[2] * SCALE_F + sBias[abs(qy1 - ky0) * RES + abs(qx1 - kx0)];
            sreg[nt][3] = s4[3] * SCALE_F + sBias[abs(qy1 - ky1) * RES + abs(qx1 - kx1)];
        }

        // --- online softmax, warp-local (quad reduction) ---
        float mx0 = m0, mx1 = m1;
        #pragma unroll
        for (int nt = 0; nt < 8; nt++) {
            mx0 = fmaxf(mx0, fmaxf(sreg[nt][0], sreg[nt][1]));
            mx1 = fmaxf(mx1, fmaxf(sreg[nt][2], sreg[nt][3]));
        }
        mx0 = fmaxf(mx0, __shfl_xor_sync(0xffffffffu, mx0, 1));
        mx0 = fmaxf(mx0, __shfl_xor_sync(0xffffffffu, mx0, 2));
        mx1 = fmaxf(mx1, __shfl_xor_sync(0xffffffffu, mx1, 1));
        mx1 = fmaxf(mx1, __shfl_xor_sync(0xffffffffu, mx1, 2));
        float a0 = __expf(m0 - mx0), a1 = __expf(m1 - mx1);
        float sum0 = 0.f, sum1 = 0.f;
        #pragma unroll
        for (int nt = 0; nt < 8; nt++) {
            float p0 = __expf(sreg[nt][0] - mx0);
            float p1 = __expf(sreg[nt][1] - mx0);
            float p2 = __expf(sreg[nt][2] - mx1);
            float p3 = __expf(sreg[nt][3] - mx1);
            sum0 += p0 + p1; sum1 += p2 + p3;
            uint2 u0 = {f2tf(p0), f2tf(p1)};
            uint2 u1 = {f2tf(p2), f2tf(p3)};
            *(uint2*)&sS[rowW * 68 + nt * 8 + 2 * t] = u0;
            *(uint2*)&sS[(rowW + 8) * 68 + nt * 8 + 2 * t] = u1;
        }
        sum0 += __shfl_xor_sync(0xffffffffu, sum0, 1);
        sum0 += __shfl_xor_sync(0xffffffffu, sum0, 2);
        sum1 += __shfl_xor_sync(0xffffffffu, sum1, 1);
        sum1 += __shfl_xor_sync(0xffffffffu, sum1, 2);
        l0 = l0 * a0 + sum0; m0 = mx0;
        l1 = l1 * a1 + sum1; m1 = mx1;

        // rescale O
        #pragma unroll
        for (int vt = 0; vt < 16; vt++) {
            o[vt][0] *= a0; o[vt][1] *= a0;
            o[vt][2] *= a1; o[vt][3] *= a1;
        }
        __syncwarp();

        // --- O += P @ V ---
        #pragma unroll
        for (int kk = 0; kk < 8; kk++) {
            uint32_t p0 = sS[rowW * 68 + kk * 8 + t];
            uint32_t p1 = sS[(rowW + 8) * 68 + kk * 8 + t];
            uint32_t p2 = sS[rowW * 68 + kk * 8 + t + 4];
            uint32_t p3 = sS[(rowW + 8) * 68 + kk * 8 + t + 4];
            #pragma unroll
            for (int vt = 0; vt < 16; vt++) {
                uint32_t b0 = sV[(kk * 8 + t) * 136 + vt * 8 + g];
                uint32_t b1 = sV[(kk * 8 + t + 4) * 136 + vt * 8 + g];
                mma8(o[vt], p0, p1, p2, p3, b0, b1);
            }
        }
        __syncthreads();   // all reads of buf[cur] done before it is refilled
    }

    // --- finalize, write O ---
    float inv0 = 1.f / l0, inv1 = 1.f / l1;
    #pragma unroll
    for (int vt = 0; vt < 16; vt++) {
        int col = vt * 8 + 2 * t;
        float2 lo = {o[vt][0] * inv0, o[vt][1] * inv0};
        float2 hi = {o[vt][2] * inv1, o[vt][3] * inv1};
        *(float2*)&g_O[(long)gRow0 * DH + h * DV + col] = lo;
        *(float2*)&g_O[(long)gRow1 * DH + h * DV + col] = hi;
    }
}

// ---------------------------------------------------------------------------
// Kernel 3: output projection. y = O @ proj_w^T + proj_b (2304 x 384, K=1024)
// ---------------------------------------------------------------------------
__global__ __launch_bounds__(256) void proj_mma(
    const float* __restrict__ Wp, const float* __restrict__ pb,
    float* __restrict__ out)
{
    __shared__ __align__(16) uint32_t sA[128 * 36];
    __shared__ __align__(16) uint32_t sB[64 * 36];

    const int tid  = threadIdx.x;
    const int warp = tid >> 5, lane = tid & 31;
    const int g = lane >> 2, t = lane & 3;
    const int warpM = warp & 3;
    const int warpN = warp >> 2;
    const int rowBase = blockIdx.x * 128;
    const int colBase = blockIdx.y * 64;

    float acc[2][4][4];
    #pragma unroll
    for (int mt = 0; mt < 2; mt++)
        #pragma unroll
        for (int nt = 0; nt < 4; nt++)
            #pragma unroll
            for (int j = 0; j < 4; j++) acc[mt][nt][j] = 0.f;

    for (int k0 = 0; k0 < DH; k0 += 32) {
        #pragma unroll
        for (int it = 0; it < 4; it++) {
            int i = tid + it * 256;
            int r = i >> 3, c = (i & 7) << 2;
            float4 a = *(const float4*)(g_O + (long)(rowBase + r) * DH + k0 + c);
            uint4 u = {f2tf(a.x), f2tf(a.y), f2tf(a.z), f2tf(a.w)};
            *(uint4*)&sA[r * 36 + c] = u;
        }
        #pragma unroll
        for (int it = 0; it < 2; it++) {
            int i = tid + it * 256;
            int r = i >> 3, c = (i & 7) << 2;
            float4 b = *(const float4*)(Wp + (long)(colBase + r) * DH + k0 + c);
            uint4 u = {f2tf(b.x), f2tf(b.y), f2tf(b.z), f2tf(b.w)};
            *(uint4*)&sB[r * 36 + c] = u;
        }
        __syncthreads();

        #pragma unroll
        for (int kk = 0; kk < 4; kk++) {
            uint32_t af[2][4], bf[4][2];
            #pragma unroll
            for (int mt = 0; mt < 2; mt++) {
                int row = warpM * 32 + mt * 16;
                af[mt][0] = sA[(row + g) * 36 + kk * 8 + t];
                af[mt][1] = sA[(row + 8 + g) * 36 + kk * 8 + t];
                af[mt][2] = sA[(row + g) * 36 + kk * 8 + t + 4];
                af[mt][3] = sA[(row + 8 + g) * 36 + kk * 8 + t + 4];
            }
            #pragma unroll
            for (int nt = 0; nt < 4; nt++) {
                int col = warpN * 32 + nt * 8;
                bf[nt][0] = sB[(col + g) * 36 + kk * 8 + t];
                bf[nt][1] = sB[(col + g) * 36 + kk * 8 + t + 4];
            }
            #pragma unroll
            for (int mt = 0; mt < 2; mt++)
                #pragma unroll
                for (int nt = 0; nt < 4; nt++)
                    mma8(acc[mt][nt], af[mt][0], af[mt][1], af[mt][2], af[mt][3],
                         bf[nt][0], bf[nt][1]);
        }
        __syncthreads();
    }

    #pragma unroll
    for (int nt = 0; nt < 4; nt++) {
        int col = colBase + warpN * 32 + nt * 8 + 2 * t;
        float b0v = pb[col], b1v = pb[col + 1];
        #pragma unroll
        for (int mt = 0; mt < 2; mt++) {
            int row0 = rowBase + warpM * 32 + mt * 16 + g;
            int row1 = row0 + 8;
            float2 lo = {acc[mt][nt][0] + b0v, acc[mt][nt][1] + b1v};
            float2 hi = {acc[mt][nt][2] + b0v, acc[mt][nt][3] + b1v};
            *(float2*)&out[row0 * DIMX + col] = lo;
            *(float2*)&out[row1 * DIMX + col] = hi;
        }
    }
}

// ---------------------------------------------------------------------------
extern "C" void kernel_launch(void* const* d_in, const int* in_sizes, int n_in,
                              void* d_out, int out_size)
{
    const float* x       = (const float*)d_in[0];
    const float* q_w     = (const float*)d_in[1];
    const float* q_b     = (const float*)d_in[2];
    const float* k_w     = (const float*)d_in[3];
    const float* k_b     = (const float*)d_in[4];
    const float* v_w     = (const float*)d_in[5];
    const float* v_b     = (const float*)d_in[6];
    const float* proj_w  = (const float*)d_in[7];
    const float* proj_b  = (const float*)d_in[8];
    const float* biases  = (const float*)d_in[9];
    float* out = (float*)d_out;

    qkv_mma<<<dim3(N_TOK / 128, 1536 / 64), 256>>>(x, q_w, q_b, k_w, k_b, v_w, v_b);

    const size_t smemBytes = AT_TOTAL * sizeof(uint32_t);
    cudaFuncSetAttribute(attn_mma, cudaFuncAttributeMaxDynamicSharedMemorySize,
                         (int)smemBytes);
    attn_mma<<<dim3(N_TOK / 128, NHEADS), 256, smemBytes>>>(biases);

    proj_mma<<<dim3(N_TOK / 128, DIMX / 64), 256>>>(proj_w, proj_b, out);
}

// round 6
// speedup vs baseline: 1.3502x; 1.0205x over previous
#include <cuda_runtime.h>
#include <cstdint>

#define N_TOK 2304
#define DIMX 384
#define NHEADS 8
#define KD 32
#define DV 128
#define DH 1024
#define RES 48
#define SCALE_F 0.17677669529663687f

// Scratch (allocation-free rule: __device__ globals)
// NOTE: g_Q/g_K/g_V hold tf32-rounded bit patterns (written by qkv epilogue).
__device__ float g_Q[NHEADS * N_TOK * KD];   // [h][n][32]
__device__ float g_K[NHEADS * N_TOK * KD];   // [h][n][32]
__device__ float g_V[NHEADS * N_TOK * DV];   // [h][n][128]
__device__ float g_O[N_TOK * DH];            // [n][h*128+d] (fp32)

// ---------------------------------------------------------------------------
// helpers
// ---------------------------------------------------------------------------
__device__ __forceinline__ uint32_t f2tf(float f) {
    uint32_t u;
    asm("cvt.rna.tf32.f32 %0, %1;" : "=r"(u) : "f"(f));
    return u;
}

__device__ __forceinline__ void mma8(float* d,
                                     uint32_t a0, uint32_t a1, uint32_t a2, uint32_t a3,
                                     uint32_t b0, uint32_t b1)
{
    asm volatile(
        "mma.sync.aligned.m16n8k8.row.col.f32.tf32.tf32.f32 "
        "{%0,%1,%2,%3}, {%4,%5,%6,%7}, {%8,%9}, {%0,%1,%2,%3};\n"
        : "+f"(d[0]), "+f"(d[1]), "+f"(d[2]), "+f"(d[3])
        : "r"(a0), "r"(a1), "r"(a2), "r"(a3), "r"(b0), "r"(b1));
}

__device__ __forceinline__ void cp16(uint32_t* smem_dst, const void* gsrc) {
    uint32_t sa = (uint32_t)__cvta_generic_to_shared(smem_dst);
    asm volatile("cp.async.cg.shared.global [%0], [%1], 16;\n" :: "r"(sa), "l"(gsrc));
}
__device__ __forceinline__ void cp_commit() {
    asm volatile("cp.async.commit_group;\n");
}
template <int N>
__device__ __forceinline__ void cp_wait() {
    asm volatile("cp.async.wait_group %0;\n" :: "n"(N));
}

// ---------------------------------------------------------------------------
// Kernel 1: fused QKV projection. C = x @ W^T + b  (2304 x 1536, K=384)
// ---------------------------------------------------------------------------
__global__ __launch_bounds__(256) void qkv_mma(
    const float* __restrict__ x,
    const float* __restrict__ q_w, const float* __restrict__ q_b,
    const float* __restrict__ k_w, const float* __restrict__ k_b,
    const float* __restrict__ v_w, const float* __restrict__ v_b)
{
    __shared__ __align__(16) uint32_t sA[128 * 36];
    __shared__ __align__(16) uint32_t sB[64 * 36];

    const int tid  = threadIdx.x;
    const int warp = tid >> 5, lane = tid & 31;
    const int g = lane >> 2, t = lane & 3;
    const int warpM = warp & 3;
    const int warpN = warp >> 2;
    const int rowBase = blockIdx.x * 128;
    const int colBase = blockIdx.y * 64;

    const float* W; const float* bias; int sel, wBase;
    if (colBase < 256)      { W = q_w; bias = q_b; sel = 0; wBase = colBase;       }
    else if (colBase < 512) { W = k_w; bias = k_b; sel = 1; wBase = colBase - 256; }
    else                    { W = v_w; bias = v_b; sel = 2; wBase = colBase - 512; }

    float acc[2][4][4];
    #pragma unroll
    for (int mt = 0; mt < 2; mt++)
        #pragma unroll
        for (int nt = 0; nt < 4; nt++)
            #pragma unroll
            for (int j = 0; j < 4; j++) acc[mt][nt][j] = 0.f;

    for (int k0 = 0; k0 < DIMX; k0 += 32) {
        #pragma unroll
        for (int it = 0; it < 4; it++) {
            int i = tid + it * 256;
            int r = i >> 3, c = (i & 7) << 2;
            float4 a = *(const float4*)(x + (rowBase + r) * DIMX + k0 + c);
            uint4 u = {f2tf(a.x), f2tf(a.y), f2tf(a.z), f2tf(a.w)};
            *(uint4*)&sA[r * 36 + c] = u;
        }
        #pragma unroll
        for (int it = 0; it < 2; it++) {
            int i = tid + it * 256;
            int r = i >> 3, c = (i & 7) << 2;
            float4 b = *(const float4*)(W + (wBase + r) * DIMX + k0 + c);
            uint4 u = {f2tf(b.x), f2tf(b.y), f2tf(b.z), f2tf(b.w)};
            *(uint4*)&sB[r * 36 + c] = u;
        }
        __syncthreads();

        #pragma unroll
        for (int kk = 0; kk < 4; kk++) {
            uint32_t af[2][4], bf[4][2];
            #pragma unroll
            for (int mt = 0; mt < 2; mt++) {
                int row = warpM * 32 + mt * 16;
                af[mt][0] = sA[(row + g) * 36 + kk * 8 + t];
                af[mt][1] = sA[(row + 8 + g) * 36 + kk * 8 + t];
                af[mt][2] = sA[(row + g) * 36 + kk * 8 + t + 4];
                af[mt][3] = sA[(row + 8 + g) * 36 + kk * 8 + t + 4];
            }
            #pragma unroll
            for (int nt = 0; nt < 4; nt++) {
                int col = warpN * 32 + nt * 8;
                bf[nt][0] = sB[(col + g) * 36 + kk * 8 + t];
                bf[nt][1] = sB[(col + g) * 36 + kk * 8 + t + 4];
            }
            #pragma unroll
            for (int mt = 0; mt < 2; mt++)
                #pragma unroll
                for (int nt = 0; nt < 4; nt++)
                    mma8(acc[mt][nt], af[mt][0], af[mt][1], af[mt][2], af[mt][3],
                         bf[nt][0], bf[nt][1]);
        }
        __syncthreads();
    }

    // epilogue: bias, then tf32-round and store bit patterns
    #pragma unroll
    for (int nt = 0; nt < 4; nt++) {
        int jl = wBase + warpN * 32 + nt * 8 + 2 * t;
        float b0v = bias[jl], b1v = bias[jl + 1];
        #pragma unroll
        for (int mt = 0; mt < 2; mt++) {
            int row0 = rowBase + warpM * 32 + mt * 16 + g;
            int row1 = row0 + 8;
            float2 lo = {__uint_as_float(f2tf(acc[mt][nt][0] + b0v)),
                         __uint_as_float(f2tf(acc[mt][nt][1] + b1v))};
            float2 hi = {__uint_as_float(f2tf(acc[mt][nt][2] + b0v)),
                         __uint_as_float(f2tf(acc[mt][nt][3] + b1v))};
            if (sel == 0) {
                int h = jl >> 5, kd = jl & 31;
                *(float2*)&g_Q[(h * N_TOK + row0) * KD + kd] = lo;
                *(float2*)&g_Q[(h * N_TOK + row1) * KD + kd] = hi;
            } else if (sel == 1) {
                int h = jl >> 5, kd = jl & 31;
                *(float2*)&g_K[(h * N_TOK + row0) * KD + kd] = lo;
                *(float2*)&g_K[(h * N_TOK + row1) * KD + kd] = hi;
            } else {
                int h = jl >> 7, dv = jl & 127;
                *(float2*)&g_V[(h * N_TOK + row0) * DV + dv] = lo;
                *(float2*)&g_V[(h * N_TOK + row1) * DV + dv] = hi;
            }
        }
    }
}

// ---------------------------------------------------------------------------
// Kernel 2: flash attention, tf32 mma. BQ=128, BK=64, 8 warps.
// S/softmax phase: warp owns 16 rows (as before), P -> sS.
// PV phase: warps re-tiled as 4 rowgroups x 2 colgroups; each warp computes a
// 32-row x 64-col O tile, reusing each V fragment across 2 m-tiles (halves
// V smem traffic). alpha / l communicated via smem.
// ---------------------------------------------------------------------------
#define KBUF (64 * 36)                   // 2304 u32 per K buffer
#define VBUF (64 * 136)                  // 8704 u32 per V buffer
#define AT_SQ    0                       // 128*36 = 4608
#define AT_SK    (AT_SQ + 128 * 36)      // 2 x 2304
#define AT_SV    (AT_SK + 2 * KBUF)      // 2 x 8704
#define AT_SS    (AT_SV + 2 * VBUF)      // 128*68 = 8704
#define AT_SBIAS (AT_SS + 128 * 68)      // 2304
#define AT_SALPHA (AT_SBIAS + N_TOK)     // 128
#define AT_SL     (AT_SALPHA + 128)      // 128
#define AT_TOTAL  (AT_SL + 128)          // 37888 u32 = 151552 bytes

__global__ __launch_bounds__(256, 1) void attn_mma(
    const float* __restrict__ biases)
{
    extern __shared__ __align__(16) uint32_t smu[];
    uint32_t* sQ = smu + AT_SQ;
    uint32_t* sKb = smu + AT_SK;
    uint32_t* sVb = smu + AT_SV;
    uint32_t* sS = smu + AT_SS;
    float*    sBias = (float*)(smu + AT_SBIAS);
    float*    sAlpha = (float*)(smu + AT_SALPHA);
    float*    sL = (float*)(smu + AT_SL);

    const int tid  = threadIdx.x;
    const int warp = tid >> 5, lane = tid & 31;
    const int g = lane >> 2, t = lane & 3;
    const int h  = blockIdx.y;
    const int q0 = blockIdx.x * 128;

    const uint32_t* gK = (const uint32_t*)(g_K + h * N_TOK * KD);
    const uint32_t* gV = (const uint32_t*)(g_V + h * N_TOK * DV);

    // --- prologue: Q tile (tf32 bits) -> smem, bias row -> smem ---
    {
        const uint4* src = (const uint4*)(g_Q + (h * N_TOK + q0) * KD);
        #pragma unroll
        for (int it = 0; it < 4; it++) {
            int i = tid + it * 256;
            int r = i >> 3, c = (i & 7) << 2;
            *(uint4*)&sQ[r * 36 + c] = src[i];
        }
        #pragma unroll
        for (int it = 0; it < 9; it++)
            sBias[tid + it * 256] = biases[h * N_TOK + tid + it * 256];
    }

    // --- prefetch tile 0 into buffer 0 ---
    {
        #pragma unroll
        for (int it = 0; it < 2; it++) {
            int i = tid + it * 256;
            int r = i >> 3, c = (i & 7) << 2;
            cp16(&sKb[r * 36 + c], gK + i * 4);
        }
        #pragma unroll
        for (int it = 0; it < 8; it++) {
            int i = tid + it * 256;
            int r = i >> 5, c = (i & 31) << 2;
            cp16(&sVb[r * 136 + c], gV + i * 4);
        }
        cp_commit();
    }
    __syncthreads();   // sQ visible

    // --- Q fragments, register resident ---
    uint32_t qf[4][4];
    {
        int row = 16 * warp + g;
        #pragma unroll
        for (int kk = 0; kk < 4; kk++) {
            qf[kk][0] = sQ[row * 36 + kk * 8 + t];
            qf[kk][1] = sQ[(row + 8) * 36 + kk * 8 + t];
            qf[kk][2] = sQ[row * 36 + kk * 8 + t + 4];
            qf[kk][3] = sQ[(row + 8) * 36 + kk * 8 + t + 4];
        }
    }

    float m0 = -1e30f, m1 = -1e30f, l0 = 0.f, l1 = 0.f;

    // PV tiling: 4 rowgroups x 2 colgroups. O = 32 rows x 64 cols per warp.
    const int prow = (warp >> 1) * 32;    // PV row base
    const int pcol = (warp & 1) * 64;     // PV col base
    float o[2][8][4];
    #pragma unroll
    for (int mt = 0; mt < 2; mt++)
        #pragma unroll
        for (int vt = 0; vt < 8; vt++)
            #pragma unroll
            for (int j = 0; j < 4; j++) o[mt][vt][j] = 0.f;

    const int rowW = 16 * warp + g;       // softmax-phase row0
    const int gRow0 = q0 + rowW;
    const int gRow1 = gRow0 + 8;
    const int qy0 = gRow0 / RES, qx0 = gRow0 - qy0 * RES;
    const int qy1 = gRow1 / RES, qx1 = gRow1 - qy1 * RES;

    const int NITER = N_TOK / 64;   // 36

    for (int ki = 0; ki < NITER; ki++) {
        const int cur = ki & 1, nxt = cur ^ 1;
        if (ki + 1 < NITER) {
            const uint32_t* gKn = gK + (ki + 1) * 64 * KD;
            const uint32_t* gVn = gV + (ki + 1) * 64 * DV;
            #pragma unroll
            for (int it = 0; it < 2; it++) {
                int i = tid + it * 256;
                int r = i >> 3, c = (i & 7) << 2;
                cp16(&sKb[nxt * KBUF + r * 36 + c], gKn + i * 4);
            }
            #pragma unroll
            for (int it = 0; it < 8; it++) {
                int i = tid + it * 256;
                int r = i >> 5, c = (i & 31) << 2;
                cp16(&sVb[nxt * VBUF + r * 136 + c], gVn + i * 4);
            }
            cp_commit();
            cp_wait<1>();
        } else {
            cp_wait<0>();
        }
        __syncthreads();

        const uint32_t* sK = sKb + cur * KBUF;
        const uint32_t* sV = sVb + cur * VBUF;
        const int k0 = ki * 64;

        // --- S = Q @ K^T (warp's 16 rows x 64) + scale + computed bias ---
        float sreg[8][4];
        #pragma unroll
        for (int nt = 0; nt < 8; nt++) {
            float s4[4] = {0.f, 0.f, 0.f, 0.f};
            #pragma unroll
            for (int kk = 0; kk < 4; kk++) {
                uint32_t b0 = sK[(nt * 8 + g) * 36 + kk * 8 + t];
                uint32_t b1 = sK[(nt * 8 + g) * 36 + kk * 8 + t + 4];
                mma8(s4, qf[kk][0], qf[kk][1], qf[kk][2], qf[kk][3], b0, b1);
            }
            int c0 = k0 + nt * 8 + 2 * t;
            int c1 = c0 + 1;
            int ky0 = c0 / RES, kx0 = c0 - ky0 * RES;
            int ky1 = c1 / RES, kx1 = c1 - ky1 * RES;
            sreg[nt][0] = s4[0] * SCALE_F + sBias[abs(qy0 - ky0) * RES + abs(qx0 - kx0)];
            sreg[nt][1] = s4[1] * SCALE_F + sBias[abs(qy0 - ky1) * RES + abs(qx0 - kx1)];
            sreg[nt][2] = s4[2] * SCALE_F + sBias[abs(qy1 - ky0) * RES + abs(qx1 - kx0)];
            sreg[nt][3] = s4[3] * SCALE_F + sBias[abs(qy1 - ky1) * RES + abs(qx1 - kx1)];
        }

        // --- online softmax, warp-local ---
        float mx0 = m0, mx1 = m1;
        #pragma unroll
        for (int nt = 0; nt < 8; nt++) {
            mx0 = fmaxf(mx0, fmaxf(sreg[nt][0], sreg[nt][1]));
            mx1 = fmaxf(mx1, fmaxf(sreg[nt][2], sreg[nt][3]));
        }
        mx0 = fmaxf(mx0, __shfl_xor_sync(0xffffffffu, mx0, 1));
        mx0 = fmaxf(mx0, __shfl_xor_sync(0xffffffffu, mx0, 2));
        mx1 = fmaxf(mx1, __shfl_xor_sync(0xffffffffu, mx1, 1));
        mx1 = fmaxf(mx1, __shfl_xor_sync(0xffffffffu, mx1, 2));
        float a0 = __expf(m0 - mx0), a1 = __expf(m1 - mx1);
        float sum0 = 0.f, sum1 = 0.f;
        #pragma unroll
        for (int nt = 0; nt < 8; nt++) {
            float p0 = __expf(sreg[nt][0] - mx0);
            float p1 = __expf(sreg[nt][1] - mx0);
            float p2 = __expf(sreg[nt][2] - mx1);
            float p3 = __expf(sreg[nt][3] - mx1);
            sum0 += p0 + p1; sum1 += p2 + p3;
            uint2 u0 = {f2tf(p0), f2tf(p1)};
            uint2 u1 = {f2tf(p2), f2tf(p3)};
            *(uint2*)&sS[rowW * 68 + nt * 8 + 2 * t] = u0;
            *(uint2*)&sS[(rowW + 8) * 68 + nt * 8 + 2 * t] = u1;
        }
        sum0 += __shfl_xor_sync(0xffffffffu, sum0, 1);
        sum0 += __shfl_xor_sync(0xffffffffu, sum0, 2);
        sum1 += __shfl_xor_sync(0xffffffffu, sum1, 1);
        sum1 += __shfl_xor_sync(0xffffffffu, sum1, 2);
        l0 = l0 * a0 + sum0; m0 = mx0;
        l1 = l1 * a1 + sum1; m1 = mx1;
        if (t == 0) {                       // one lane per row writes alpha
            sAlpha[rowW] = a0;
            sAlpha[rowW + 8] = a1;
        }
        __syncthreads();   // sS + sAlpha visible to PV-tiled warps

        // --- rescale O (PV tiling rows) ---
        #pragma unroll
        for (int mt = 0; mt < 2; mt++) {
            float al0 = sAlpha[prow + mt * 16 + g];
            float al1 = sAlpha[prow + mt * 16 + 8 + g];
            #pragma unroll
            for (int vt = 0; vt < 8; vt++) {
                o[mt][vt][0] *= al0; o[mt][vt][1] *= al0;
                o[mt][vt][2] *= al1; o[mt][vt][3] *= al1;
            }
        }

        // --- O += P @ V : V fragments reused across 2 m-tiles ---
        #pragma unroll
        for (int kk = 0; kk < 8; kk++) {
            uint32_t pa[2][4];
            #pragma unroll
            for (int mt = 0; mt < 2; mt++) {
                int r = prow + mt * 16 + g;
                pa[mt][0] = sS[r * 68 + kk * 8 + t];
                pa[mt][1] = sS[(r + 8) * 68 + kk * 8 + t];
                pa[mt][2] = sS[r * 68 + kk * 8 + t + 4];
                pa[mt][3] = sS[(r + 8) * 68 + kk * 8 + t + 4];
            }
            #pragma unroll
            for (int vt = 0; vt < 8; vt++) {
                uint32_t b0 = sV[(kk * 8 + t) * 136 + pcol + vt * 8 + g];
                uint32_t b1 = sV[(kk * 8 + t + 4) * 136 + pcol + vt * 8 + g];
                mma8(o[0][vt], pa[0][0], pa[0][1], pa[0][2], pa[0][3], b0, b1);
                mma8(o[1][vt], pa[1][0], pa[1][1], pa[1][2], pa[1][3], b0, b1);
            }
        }
        __syncthreads();   // buf[cur] + sS reads done before refill/rewrite
    }

    // --- publish l, then finalize with PV tiling ---
    if (t == 0) {
        sL[rowW] = l0;
        sL[rowW + 8] = l1;
    }
    __syncthreads();
    #pragma unroll
    for (int mt = 0; mt < 2; mt++) {
        int r0 = prow + mt * 16 + g;
        int r1 = r0 + 8;
        float inv0 = 1.f / sL[r0];
        float inv1 = 1.f / sL[r1];
        #pragma unroll
        for (int vt = 0; vt < 8; vt++) {
            int col = pcol + vt * 8 + 2 * t;
            float2 lo = {o[mt][vt][0] * inv0, o[mt][vt][1] * inv0};
            float2 hi = {o[mt][vt][2] * inv1, o[mt][vt][3] * inv1};
            *(float2*)&g_O[(long)(q0 + r0) * DH + h * DV + col] = lo;
            *(float2*)&g_O[(long)(q0 + r1) * DH + h * DV + col] = hi;
        }
    }
}

// ---------------------------------------------------------------------------
// Kernel 3: output projection. y = O @ proj_w^T + proj_b (2304 x 384, K=1024)
// ---------------------------------------------------------------------------
__global__ __launch_bounds__(256) void proj_mma(
    const float* __restrict__ Wp, const float* __restrict__ pb,
    float* __restrict__ out)
{
    __shared__ __align__(16) uint32_t sA[128 * 36];
    __shared__ __align__(16) uint32_t sB[64 * 36];

    const int tid  = threadIdx.x;
    const int warp = tid >> 5, lane = tid & 31;
    const int g = lane >> 2, t = lane & 3;
    const int warpM = warp & 3;
    const int warpN = warp >> 2;
    const int rowBase = blockIdx.x * 128;
    const int colBase = blockIdx.y * 64;

    float acc[2][4][4];
    #pragma unroll
    for (int mt = 0; mt < 2; mt++)
        #pragma unroll
        for (int nt = 0; nt < 4; nt++)
            #pragma unroll
            for (int j = 0; j < 4; j++) acc[mt][nt][j] = 0.f;

    for (int k0 = 0; k0 < DH; k0 += 32) {
        #pragma unroll
        for (int it = 0; it < 4; it++) {
            int i = tid + it * 256;
            int r = i >> 3, c = (i & 7) << 2;
            float4 a = *(const float4*)(g_O + (long)(rowBase + r) * DH + k0 + c);
            uint4 u = {f2tf(a.x), f2tf(a.y), f2tf(a.z), f2tf(a.w)};
            *(uint4*)&sA[r * 36 + c] = u;
        }
        #pragma unroll
        for (int it = 0; it < 2; it++) {
            int i = tid + it * 256;
            int r = i >> 3, c = (i & 7) << 2;
            float4 b = *(const float4*)(Wp + (long)(colBase + r) * DH + k0 + c);
            uint4 u = {f2tf(b.x), f2tf(b.y), f2tf(b.z), f2tf(b.w)};
            *(uint4*)&sB[r * 36 + c] = u;
        }
        __syncthreads();

        #pragma unroll
        for (int kk = 0; kk < 4; kk++) {
            uint32_t af[2][4], bf[4][2];
            #pragma unroll
            for (int mt = 0; mt < 2; mt++) {
                int row = warpM * 32 + mt * 16;
                af[mt][0] = sA[(row + g) * 36 + kk * 8 + t];
                af[mt][1] = sA[(row + 8 + g) * 36 + kk * 8 + t];
                af[mt][2] = sA[(row + g) * 36 + kk * 8 + t + 4];
                af[mt][3] = sA[(row + 8 + g) * 36 + kk * 8 + t + 4];
            }
            #pragma unroll
            for (int nt = 0; nt < 4; nt++) {
                int col = warpN * 32 + nt * 8;
                bf[nt][0] = sB[(col + g) * 36 + kk * 8 + t];
                bf[nt][1] = sB[(col + g) * 36 + kk * 8 + t + 4];
            }
            #pragma unroll
            for (int mt = 0; mt < 2; mt++)
                #pragma unroll
                for (int nt = 0; nt < 4; nt++)
                    mma8(acc[mt][nt], af[mt][0], af[mt][1], af[mt][2], af[mt][3],
                         bf[nt][0], bf[nt][1]);
        }
        __syncthreads();
    }

    #pragma unroll
    for (int nt = 0; nt < 4; nt++) {
        int col = colBase + warpN * 32 + nt * 8 + 2 * t;
        float b0v = pb[col], b1v = pb[col + 1];
        #pragma unroll
        for (int mt = 0; mt < 2; mt++) {
            int row0 = rowBase + warpM * 32 + mt * 16 + g;
            int row1 = row0 + 8;
            float2 lo = {acc[mt][nt][0] + b0v, acc[mt][nt][1] + b1v};
            float2 hi = {acc[mt][nt][2] + b0v, acc[mt][nt][3] + b1v};
            *(float2*)&out[row0 * DIMX + col] = lo;
            *(float2*)&out[row1 * DIMX + col] = hi;
        }
    }
}

// ---------------------------------------------------------------------------
extern "C" void kernel_launch(void* const* d_in, const int* in_sizes, int n_in,
                              void* d_out, int out_size)
{
    const float* x       = (const float*)d_in[0];
    const float* q_w     = (const float*)d_in[1];
    const float* q_b     = (const float*)d_in[2];
    const float* k_w     = (const float*)d_in[3];
    const float* k_b     = (const float*)d_in[4];
    const float* v_w     = (const float*)d_in[5];
    const float* v_b     = (const float*)d_in[6];
    const float* proj_w  = (const float*)d_in[7];
    const float* proj_b  = (const float*)d_in[8];
    const float* biases  = (const float*)d_in[9];
    float* out = (float*)d_out;

    qkv_mma<<<dim3(N_TOK / 128, 1536 / 64), 256>>>(x, q_w, q_b, k_w, k_b, v_w, v_b);

    const size_t smemBytes = AT_TOTAL * sizeof(uint32_t);
    cudaFuncSetAttribute(attn_mma, cudaFuncAttributeMaxDynamicSharedMemorySize,
                         (int)smemBytes);
    attn_mma<<<dim3(N_TOK / 128, NHEADS), 256, smemBytes>>>(biases);

    proj_mma<<<dim3(N_TOK / 128, DIMX / 64), 256>>>(proj_w, proj_b, out);
}